// round 14
// baseline (speedup 1.0000x reference)
#include <cuda_runtime.h>
#include <cuda_fp16.h>
#include <stdint.h>

#define Bb 4
#define Nn 256
#define Dd 32
#define Hh 512
#define Kk 256
#define GRID_MAIN 296

// device scratch
__device__ uint4 g_tmph[((size_t)Bb*Nn*Hh*Dd*2)/16];   // fp16 TMP per SLOT [s][h 512][c 32]
__device__ uint4 g_w2t [(16*Kk*64)/16];                 // 256 KB fp16 W2^T: 16 chunks [k 256 x 32h]
__device__ uint4 g_w1h [(16384*64)/16];                 // 1 MB fp16 W1 rows, zjS-style swizzle
__device__ int   g_jlist[Bb*Nn];
__device__ int   g_jcnt[Bb];
__device__ int   g_gilist[Bb*Nn];
__device__ int   g_slot[Bb*Nn];
__device__ int   g_total;
__device__ int   g_unit[Bb*Nn*4];                       // (slot<<4)|jt, grouped by slot
__device__ int   g_U;

// ---------------- helpers ----------------
__device__ __forceinline__ uint32_t s2u(const void* p) {
    uint32_t a;
    asm("{ .reg .u64 t; cvta.to.shared.u64 t, %1; cvt.u32.u64 %0, t; }" : "=r"(a) : "l"(p));
    return a;
}
__device__ __forceinline__ void mbar_init(uint32_t m, uint32_t c) {
    asm volatile("mbarrier.init.shared.b64 [%0], %1;" :: "r"(m), "r"(c) : "memory");
}
__device__ __forceinline__ void mbar_expect(uint32_t m, uint32_t bytes) {
    asm volatile("mbarrier.arrive.expect_tx.shared.b64 _, [%0], %1;" :: "r"(m), "r"(bytes) : "memory");
}
__device__ __forceinline__ void mbar_wait(uint32_t m, uint32_t ph) {
    asm volatile(
        "{\n\t.reg .pred P;\n\t"
        "LW%=:\n\t"
        "mbarrier.try_wait.parity.shared.b64 P, [%0], %1, 0x989680;\n\t"
        "@P bra LD%=;\n\t"
        "bra LW%=;\n\t"
        "LD%=:\n\t}"
        :: "r"(m), "r"(ph) : "memory");
}
__device__ __forceinline__ void bulk_g2s(uint32_t dst, const void* src, uint32_t bytes, uint32_t mbar) {
    asm volatile("cp.async.bulk.shared::cluster.global.mbarrier::complete_tx::bytes [%0], [%1], %2, [%3];"
                 :: "r"(dst), "l"(src), "r"(bytes), "r"(mbar) : "memory");
}
__device__ __forceinline__ void mma16816(float d[4], const uint32_t a[4], uint32_t b0, uint32_t b1) {
    asm volatile("mma.sync.aligned.m16n8k16.row.col.f32.f16.f16.f32 "
                 "{%0,%1,%2,%3}, {%4,%5,%6,%7}, {%8,%9}, {%0,%1,%2,%3};"
                 : "+f"(d[0]), "+f"(d[1]), "+f"(d[2]), "+f"(d[3])
                 : "r"(a[0]), "r"(a[1]), "r"(a[2]), "r"(a[3]), "r"(b0), "r"(b1));
}
__device__ __forceinline__ void ldsm4(uint32_t r[4], uint32_t addr) {
    asm volatile("ldmatrix.sync.aligned.m8n8.x4.shared.b16 {%0,%1,%2,%3}, [%4];"
                 : "=r"(r[0]), "=r"(r[1]), "=r"(r[2]), "=r"(r[3]) : "r"(addr));
}

// ---------------- fused prep (out_init + w2t + w1h) ----------------
__global__ void __launch_bounds__(256) prep_all_kernel(float* __restrict__ out,
                                                       const float* __restrict__ W2,
                                                       const float* __restrict__ W1) {
    __shared__ float tile2[16 * 289];
    const int blk = blockIdx.x;
    const int t   = threadIdx.x;

    if (blk < 512) {
        int idx = blk * 256 + t;
        float4* o4 = (float4*)out;
        float v = (idx < 65536) ? 0.5f : 0.f;
        o4[idx] = make_float4(v, v, v, v);
        return;
    }
    if (blk < 768) {
        int idx = (blk - 512) * 256 + t;
        int hc2 = idx >> 12;
        int rem = idx & 4095;
        int k   = rem >> 4;
        int hp  = (rem & 15) * 2;
        int h   = hc2 * 32 + hp;
        __half2 v = __floats2half2_rn(W2[h * Kk + k], W2[(h + 1) * Kk + k]);
        uint32_t byt = (uint32_t)hc2 * 16384u + (uint32_t)k * 64u
                     + (((uint32_t)hp * 2u) ^ ((((uint32_t)k >> 1) & 3u) << 4));
        *(__half2*)((char*)g_w2t + byt) = v;
        return;
    }
    const int q  = blk - 768;
    const int ht = q >> 2;
    const int aq = q & 3;
    #pragma unroll
    for (int l = 0; l < 16; l++) {
        int idx = t + 256 * l;
        int hl = idx & 15, rowl = idx >> 4;
        int a_l = rowl >> 5, c = rowl & 31;
        int grow = (aq * 8 + a_l) * 32 + c;
        tile2[hl * 289 + c * 9 + a_l] = W1[grow * Hh + ht * 16 + hl];
    }
    __syncthreads();
    #pragma unroll
    for (int l = 0; l < 8; l++) {
        int idx = t + 256 * l;
        int a2l = idx & 3, rl = idx >> 2;
        int hl = ((rl >> 6) << 1) + ((rl >> 5) & 1);
        int c  = rl & 31;
        int a2 = aq * 4 + a2l;
        float v0 = tile2[hl * 289 + c * 9 + 2 * a2l];
        float v1 = tile2[hl * 289 + c * 9 + 2 * a2l + 1];
        uint32_t byt = (uint32_t)(ht * 512 + rl) * 64u
                     + (((uint32_t)a2 * 4u) ^ ((((uint32_t)rl >> 1) & 3u) << 4));
        *(__half2*)((char*)g_w1h + byt) = __floats2half2_rn(v0, v1);
    }
}

__global__ void __launch_bounds__(1024) prep_mask_kernel(const float* __restrict__ mm) {
    __shared__ int wcnt[32], woff[33];
    __shared__ int ubase[4], sbase[4], ntl[4];
    int t = threadIdx.x, w = t >> 5, lane = t & 31, b = t >> 8;
    int act = (mm[t] != 0.f);
    unsigned bal = __ballot_sync(0xffffffffu, act);
    if (lane == 0) wcnt[w] = __popc(bal);
    __syncthreads();
    if (t == 0) {
        int s = 0;
        for (int q = 0; q < 32; q++) { woff[q] = s; s += wcnt[q]; }
        woff[32] = s; g_total = s;
        int ub = 0;
        for (int bb = 0; bb < 4; bb++) {
            int jc = woff[bb * 8 + 8] - woff[bb * 8];
            g_jcnt[bb] = jc;
            sbase[bb] = woff[bb * 8];
            int nt = (jc + 63) >> 6;
            ntl[bb] = nt;
            ubase[bb] = ub;
            ub += jc * nt;
        }
        g_U = ub;
    }
    __syncthreads();
    if (act) {
        int pg = woff[w] + __popc(bal & ((1u << lane) - 1u));
        g_jlist[b * Nn + (pg - woff[b * 8])] = t & 255;
        g_gilist[pg] = t;
        g_slot[t] = pg;
        int nt = ntl[b];
        int ub = ubase[b] + (pg - sbase[b]) * nt;
        for (int jt = 0; jt < nt; jt++) g_unit[ub + jt] = (pg << 4) | jt;
    }
}

// TMP via HMMA (unchanged from R13)
#define PM_ZA   0
#define PM_B    4096
#define PM_STG  12288
#define PM_SMEM 20480
__global__ void __launch_bounds__(256) prep_tmpmma_kernel(const float* __restrict__ z) {
    extern __shared__ char psm[];
    __shared__ __align__(8) uint64_t pmb[2];
    __shared__ int giS2[64];

    const int total = g_total;
    const int it = blockIdx.x;
    if (it * 64 >= total) return;
    const int fc = blockIdx.y;
    const int t  = threadIdx.x;
    const int w    = t >> 5;
    const int lane = t & 31;
    const int wr   = w >> 2;
    const int wc   = w & 3;
    const int lr   = lane >> 2;
    const int lc   = (lane & 3) * 2;
    const int mrow = lane & 7;
    const int mg   = lane >> 3;

    const uint32_t smb = s2u(psm);
    const uint32_t mb  = s2u(pmb);

    if (t < 64) giS2[t] = (it * 64 + t < total) ? g_gilist[it * 64 + t] : -1;
    if (t == 0) { mbar_init(mb, 1); mbar_init(mb + 8, 1); }
    __syncthreads();

    if (t < 64) {
        char* zr = psm + PM_ZA + t * 64;
        uint32_t sw = (((uint32_t)t >> 1) & 3u) << 4;
        int gi = giS2[t];
        if (gi >= 0) {
            const float4* zp = (const float4*)(z + (size_t)gi * Dd);
            #pragma unroll
            for (int c4 = 0; c4 < 8; c4++) {
                float4 v = zp[c4];
                *(__half2*)(zr + (((uint32_t)(c4 * 8))     ^ sw)) = __floats2half2_rn(v.x, v.y);
                *(__half2*)(zr + (((uint32_t)(c4 * 8 + 4)) ^ sw)) = __floats2half2_rn(v.z, v.w);
            }
        } else {
            #pragma unroll
            for (int c4 = 0; c4 < 8; c4++) {
                *(__half2*)(zr + (((uint32_t)(c4 * 8))     ^ sw)) = __floats2half2_rn(0.f, 0.f);
                *(__half2*)(zr + (((uint32_t)(c4 * 8 + 4)) ^ sw)) = __floats2half2_rn(0.f, 0.f);
            }
        }
    }
    if (t == 0) {
        mbar_expect(mb, 4096);
        bulk_g2s(smb + PM_B,        (const char*)g_w1h + (size_t)(fc * 16 + 0) * 4096, 4096, mb);
        mbar_expect(mb + 8, 4096);
        bulk_g2s(smb + PM_B + 4096, (const char*)g_w1h + (size_t)(fc * 16 + 1) * 4096, 4096, mb + 8);
    }
    __syncthreads();

    int pw[2] = {0, 0};
    for (int q = 0; q < 16; q++) {
        const int buf = q & 1;
        mbar_wait(mb + buf * 8, pw[buf] & 1); pw[buf]++;
        __syncthreads();

        float acc1[2][2][4];
        #pragma unroll
        for (int mt = 0; mt < 2; mt++)
            #pragma unroll
            for (int nt = 0; nt < 2; nt++)
                #pragma unroll
                for (int e = 0; e < 4; e++) acc1[mt][nt][e] = 0.f;

        const uint32_t bbase = smb + PM_B + (uint32_t)buf * 4096u;
        #pragma unroll
        for (int kk = 0; kk < 2; kk++) {
            const uint32_t cb = (uint32_t)((kk * 16 + (mg >> 1) * 8) * 2);
            uint32_t bf[4];
            {
                int nh = wc * 16 + (mg & 1) * 8 + mrow;
                ldsm4(bf, bbase + (uint32_t)nh * 64u + (cb ^ ((((uint32_t)nh >> 1) & 3u) << 4)));
            }
            #pragma unroll
            for (int mt = 0; mt < 2; mt++) {
                uint32_t af[4];
                int jr = wr * 32 + mt * 16 + (mg & 1) * 8 + mrow;
                ldsm4(af, smb + PM_ZA + (uint32_t)jr * 64u + (cb ^ ((((uint32_t)jr >> 1) & 3u) << 4)));
                mma16816(acc1[mt][0], af, bf[0], bf[2]);
                mma16816(acc1[mt][1], af, bf[1], bf[3]);
            }
        }

        #pragma unroll
        for (int mt = 0; mt < 2; mt++)
            #pragma unroll
            for (int nt = 0; nt < 2; nt++) {
                int rl = wr * 32 + mt * 16 + lr;
                int hl = wc * 16 + nt * 8 + lc;
                uint32_t sw = ((uint32_t)rl & 7u) << 4;
                *(__half2*)(psm + PM_STG + rl * 128 + (((uint32_t)(hl * 2)) ^ sw))
                    = __floats2half2_rn(acc1[mt][nt][0], acc1[mt][nt][1]);
                *(__half2*)(psm + PM_STG + (rl + 8) * 128 + (((uint32_t)(hl * 2)) ^ sw))
                    = __floats2half2_rn(acc1[mt][nt][2], acc1[mt][nt][3]);
            }
        __syncthreads();

        if (t == 0 && q + 2 < 16) {
            mbar_expect(mb + buf * 8, 4096);
            bulk_g2s(smb + PM_B + (uint32_t)buf * 4096u,
                     (const char*)g_w1h + (size_t)(fc * 16 + q + 2) * 4096, 4096, mb + buf * 8);
        }

        const int qg = fc * 16 + q;
        #pragma unroll
        for (int l = 0; l < 2; l++) {
            int idx = t + 256 * l;
            int sl = idx >> 3, qt = idx & 7;
            int s = it * 64 + sl;
            if (s < total) {
                uint4 v = *(const uint4*)(psm + PM_STG + sl * 128 + ((qt * 16) ^ ((sl & 7) << 4)));
                *(uint4*)((char*)g_tmph + (size_t)s * 32768 + qg * 128 + qt * 16) = v;
            }
        }
    }
}

// ---------------- main kernel (persistent, pipelined, 1 bar/chunk) ----------------
// dyn smem: zjS 4K @0 | tmpS 32K @4096 | W2 ring 3x16K @36864 | h1 2x8K @86016 = 102400
#define ZJ_OFF  0
#define TMP_OFF 4096
#define W2_OFF  36864
#define H1_OFF  86016
#define MAIN_SMEM 102400

// MMA1 for one 64h chunk (hc) of current unit: reads zjS/tmpS, writes bias+relu fp16 into h1p.
__device__ __forceinline__ void mma1_chunk(uint32_t smb, char* dsm, const float* b1s,
                                           int hc, char* h1p,
                                           int wr, int wc, int lr, int lc, int mrow, int mg)
{
    float acc1[2][2][4];
    #pragma unroll
    for (int mt = 0; mt < 2; mt++)
        #pragma unroll
        for (int nt = 0; nt < 2; nt++)
            #pragma unroll
            for (int e = 0; e < 4; e++) acc1[mt][nt][e] = 0.f;

    #pragma unroll
    for (int kk = 0; kk < 2; kk++) {
        const uint32_t cb = (uint32_t)((kk * 16 + (mg >> 1) * 8) * 2);
        uint32_t bf[4];
        {
            int nh = hc * 64 + wc * 16 + (mg & 1) * 8 + mrow;
            ldsm4(bf, smb + TMP_OFF + (uint32_t)nh * 64u + (cb ^ ((((uint32_t)nh >> 1) & 3u) << 4)));
        }
        #pragma unroll
        for (int mt = 0; mt < 2; mt++) {
            uint32_t af[4];
            int jr = wr * 32 + mt * 16 + (mg & 1) * 8 + mrow;
            ldsm4(af, smb + ZJ_OFF + (uint32_t)jr * 64u + (cb ^ ((((uint32_t)jr >> 1) & 3u) << 4)));
            mma16816(acc1[mt][0], af, bf[0], bf[2]);
            mma16816(acc1[mt][1], af, bf[1], bf[3]);
        }
    }
    #pragma unroll
    for (int mt = 0; mt < 2; mt++)
        #pragma unroll
        for (int nt = 0; nt < 2; nt++) {
            int rl = wr * 32 + mt * 16 + lr;
            int hl = wc * 16 + nt * 8 + lc;
            int hg = hc * 64 + hl;
            uint32_t sw = ((uint32_t)rl & 7u) << 4;
            float v0 = fmaxf(acc1[mt][nt][0] + b1s[hg],     0.f);
            float v1 = fmaxf(acc1[mt][nt][1] + b1s[hg + 1], 0.f);
            float v2 = fmaxf(acc1[mt][nt][2] + b1s[hg],     0.f);
            float v3 = fmaxf(acc1[mt][nt][3] + b1s[hg + 1], 0.f);
            *(__half2*)(h1p + rl * 128 + (((uint32_t)(hl * 2)) ^ sw))       = __floats2half2_rn(v0, v1);
            *(__half2*)(h1p + (rl + 8) * 128 + (((uint32_t)(hl * 2)) ^ sw)) = __floats2half2_rn(v2, v3);
        }
}

__global__ void __launch_bounds__(256, 2)
decoder_hmma_kernel(const float* __restrict__ z, const float* __restrict__ b1,
                    const float* __restrict__ b2, const float* __restrict__ W3,
                    const float* __restrict__ b3, float* __restrict__ out)
{
    extern __shared__ char dsm[];
    __shared__ float b1s[512], b2s[256], w3s[256], part[64];
    __shared__ int jlS[256];
    __shared__ __align__(8) uint64_t mbars[3];

    const int t    = threadIdx.x;
    const int w    = t >> 5;
    const int lane = t & 31;
    const int wr   = w >> 2;
    const int wc   = w & 3;
    const int lr   = lane >> 2;
    const int lc   = (lane & 3) * 2;
    const int mrow = lane & 7;
    const int mg   = lane >> 3;

    const int U  = g_U;
    const int u0 = (int)(((long long)blockIdx.x * U) / GRID_MAIN);
    const int u1 = (int)(((long long)(blockIdx.x + 1) * U) / GRID_MAIN);
    if (u0 >= u1) return;
    const int totalQ = (u1 - u0) * 16;

    const uint32_t smb = s2u(dsm);
    const uint32_t mb0 = s2u(mbars);

    for (int k = t; k < 512; k += 256) b1s[k] = b1[k];
    b2s[t] = b2[t];
    w3s[t] = W3[t];
    if (t == 0) { mbar_init(mb0, 1); mbar_init(mb0 + 8, 1); mbar_init(mb0 + 16, 1); }
    __syncthreads();
    if (t == 0) {                       // prime ring: subs 0,1,2
        int np = totalQ < 3 ? totalQ : 3;
        for (int q = 0; q < np; q++) {
            mbar_expect(mb0 + 8u * q, 16384);
            bulk_g2s(smb + W2_OFF + (uint32_t)q * 16384u,
                     (const char*)g_w2t + (q & 15) * 16384, 16384, mb0 + 8u * q);
        }
    }

    const float b3v = b3[0];
    int C = 0;
    int bprev = -1, sprev = -1;

    for (int u = u0; u < u1; u++) {
        const int enc = g_unit[u];
        const int s   = enc >> 4;
        const int jt  = enc & 15;
        const int gi  = g_gilist[s];
        const int b   = gi >> 8;

        if (b != bprev) {
            jlS[t] = g_jlist[b * Nn + t];
            bprev = b;
            __syncthreads();
        }
        const int Kact = g_jcnt[b];

        if (s != sprev) {               // tmpS: 512 rows x 64B, swizzle ((row>>1)&3)<<4
            const char* gsrc = (const char*)g_tmph + (size_t)s * 32768;
            #pragma unroll
            for (int r8 = 0; r8 < 8; r8++) {
                int idx = t + 256 * r8;
                int row = idx >> 2, q = idx & 3;
                uint4 v = *(const uint4*)(gsrc + row * 64 + q * 16);
                *(uint4*)(dsm + TMP_OFF + row * 64 + ((q * 16) ^ (((row >> 1) & 3) << 4))) = v;
            }
            sprev = s;
        }

        if (t < 64) {                   // zjS + part zero
            part[t] = 0.f;
            int idx = jt * 64 + t;
            char* zr = dsm + ZJ_OFF + t * 64;
            uint32_t sw = (((uint32_t)t >> 1) & 3u) << 4;
            if (idx < Kact) {
                const float4* zp = (const float4*)(z + ((size_t)b * Nn + jlS[idx]) * Dd);
                #pragma unroll
                for (int c4 = 0; c4 < 8; c4++) {
                    float4 v = zp[c4];
                    *(__half2*)(zr + (((uint32_t)(c4 * 8))     ^ sw)) = __floats2half2_rn(v.x, v.y);
                    *(__half2*)(zr + (((uint32_t)(c4 * 8 + 4)) ^ sw)) = __floats2half2_rn(v.z, v.w);
                }
            } else {
                #pragma unroll
                for (int c4 = 0; c4 < 8; c4++) {
                    *(__half2*)(zr + (((uint32_t)(c4 * 8))     ^ sw)) = __floats2half2_rn(0.f, 0.f);
                    *(__half2*)(zr + (((uint32_t)(c4 * 8 + 4)) ^ sw)) = __floats2half2_rn(0.f, 0.f);
                }
            }
        }
        __syncthreads();                // refills visible

        // prologue: MMA1 chunk 0 into h1 buf[C&1], then make it visible
        mma1_chunk(smb, dsm, b1s, 0, dsm + H1_OFF + (C & 1) * 8192, wr, wc, lr, lc, mrow, mg);
        __syncthreads();

        float acc2[2][8][4];
        #pragma unroll
        for (int mt = 0; mt < 2; mt++)
            #pragma unroll
            for (int nt = 0; nt < 8; nt++)
                #pragma unroll
                for (int e = 0; e < 4; e++) acc2[mt][nt][e] = 0.f;

        for (int hc = 0; hc < 8; hc++) {
            // lookahead MMA1 for next chunk (gives TMA slack too)
            if (hc < 7)
                mma1_chunk(smb, dsm, b1s, hc + 1, dsm + H1_OFF + ((C + 1) & 1) * 8192,
                           wr, wc, lr, lc, mrow, mg);

            const int q0 = 2 * C, q1 = 2 * C + 1;
            const uint32_t s0 = (uint32_t)(q0 % 3), s1 = (uint32_t)(q1 % 3);
            mbar_wait(mb0 + s0 * 8u, (q0 / 3) & 1);
            mbar_wait(mb0 + s1 * 8u, (q1 / 3) & 1);

            // MMA2: both 32h halves back-to-back
            const uint32_t sb0 = smb + W2_OFF + s0 * 16384u;
            const uint32_t sb1 = smb + W2_OFF + s1 * 16384u;
            const uint32_t h1b = smb + H1_OFF + (uint32_t)(C & 1) * 8192u;
            #pragma unroll
            for (int kkg = 0; kkg < 4; kkg++) {
                const uint32_t kb = (uint32_t)((((kkg & 1) * 16) + (mg >> 1) * 8) * 2);
                const uint32_t hb = (uint32_t)((kkg * 16 + (mg >> 1) * 8) * 2);
                const uint32_t wbase = (kkg < 2) ? sb0 : sb1;
                uint32_t bfs[4][4];
                #pragma unroll
                for (int p = 0; p < 4; p++) {
                    int n = wc * 64 + p * 16 + (mg & 1) * 8 + mrow;
                    ldsm4(bfs[p], wbase + (uint32_t)n * 64u + (kb ^ ((((uint32_t)n >> 1) & 3u) << 4)));
                }
                #pragma unroll
                for (int mt = 0; mt < 2; mt++) {
                    uint32_t af[4];
                    int rl = wr * 32 + mt * 16 + (mg & 1) * 8 + mrow;
                    ldsm4(af, h1b + (uint32_t)rl * 128u + (hb ^ (((uint32_t)rl & 7u) << 4)));
                    #pragma unroll
                    for (int p = 0; p < 4; p++) {
                        mma16816(acc2[mt][2 * p],     af, bfs[p][0], bfs[p][2]);
                        mma16816(acc2[mt][2 * p + 1], af, bfs[p][1], bfs[p][3]);
                    }
                }
            }

            __syncthreads();            // orders: h1(C+1) visible, ring slots of C free, part/next
            if (t == 0) {               // prefetch subs 2C+3, 2C+4 into just-freed slots
                int qa = 2 * C + 3, qb = 2 * C + 4;
                if (qa < totalQ) {
                    mbar_expect(mb0 + (uint32_t)(qa % 3) * 8u, 16384);
                    bulk_g2s(smb + W2_OFF + (uint32_t)(qa % 3) * 16384u,
                             (const char*)g_w2t + (qa & 15) * 16384, 16384,
                             mb0 + (uint32_t)(qa % 3) * 8u);
                }
                if (qb < totalQ) {
                    mbar_expect(mb0 + (uint32_t)(qb % 3) * 8u, 16384);
                    bulk_g2s(smb + W2_OFF + (uint32_t)(qb % 3) * 16384u,
                             (const char*)g_w2t + (qb & 15) * 16384, 16384,
                             mb0 + (uint32_t)(qb % 3) * 8u);
                }
            }
            C++;
        }

        // ---- epilogue ----
        float sacc[2][2] = {{0.f, 0.f}, {0.f, 0.f}};
        #pragma unroll
        for (int mt = 0; mt < 2; mt++)
            #pragma unroll
            for (int nt = 0; nt < 8; nt++) {
                int k = wc * 64 + nt * 8 + lc;
                sacc[mt][0] += fmaxf(acc2[mt][nt][0] + b2s[k],     0.f) * w3s[k]
                             + fmaxf(acc2[mt][nt][1] + b2s[k + 1], 0.f) * w3s[k + 1];
                sacc[mt][1] += fmaxf(acc2[mt][nt][2] + b2s[k],     0.f) * w3s[k]
                             + fmaxf(acc2[mt][nt][3] + b2s[k + 1], 0.f) * w3s[k + 1];
            }
        #pragma unroll
        for (int off = 1; off <= 2; off <<= 1) {
            #pragma unroll
            for (int mt = 0; mt < 2; mt++) {
                sacc[mt][0] += __shfl_xor_sync(0xffffffffu, sacc[mt][0], off);
                sacc[mt][1] += __shfl_xor_sync(0xffffffffu, sacc[mt][1], off);
            }
        }
        if ((lane & 3) == 0) {
            #pragma unroll
            for (int mt = 0; mt < 2; mt++) {
                int r0 = wr * 32 + mt * 16 + lr;
                atomicAdd(&part[r0],     sacc[mt][0]);
                atomicAdd(&part[r0 + 8], sacc[mt][1]);
            }
        }
        __syncthreads();
        if (t < 64) {
            int idx = jt * 64 + t;
            if (idx < Kact) {
                int j = jlS[idx];
                float lg = part[t] + b3v;
                size_t o = (size_t)gi * Nn + j;
                out[o] = 1.f / (1.f + __expf(-lg));
                out[(size_t)Bb * Nn * Nn + o] = lg;
            }
        }
        __syncthreads();
    }
}

extern "C" void kernel_launch(void* const* d_in, const int* in_sizes, int n_in,
                              void* d_out, int out_size)
{
    const float* z   = (const float*)d_in[0];
    const float* mmk = (const float*)d_in[1];
    const float* W1  = (const float*)d_in[3];
    const float* b1  = (const float*)d_in[4];
    const float* W2  = (const float*)d_in[5];
    const float* b2  = (const float*)d_in[6];
    const float* W3  = (const float*)d_in[7];
    const float* b3  = (const float*)d_in[8];
    float* out = (float*)d_out;

    cudaFuncSetAttribute(decoder_hmma_kernel,
                         cudaFuncAttributeMaxDynamicSharedMemorySize, MAIN_SMEM);

    prep_all_kernel<<<896, 256>>>(out, W2, W1);
    prep_mask_kernel<<<1, 1024>>>(mmk);
    prep_tmpmma_kernel<<<dim3(8, 16), 256, PM_SMEM>>>(z);
    decoder_hmma_kernel<<<GRID_MAIN, 256, MAIN_SMEM>>>(z, b1, b2, W3, b3, out);
}

// round 16
// speedup vs baseline: 1.0302x; 1.0302x over previous
#include <cuda_runtime.h>
#include <cuda_fp16.h>
#include <stdint.h>

#define Bb 4
#define Nn 256
#define Dd 32
#define Hh 512
#define Kk 256
#define GRID_MAIN 296

// device scratch
__device__ uint4 g_tmph[((size_t)Bb*Nn*Hh*Dd*2)/16];   // fp16 TMP per SLOT [s][h 512][c 32]
__device__ uint4 g_w2t [(16*Kk*64)/16];                 // 256 KB fp16 W2^T: 16 chunks [k 256 x 32h]
__device__ uint4 g_w1h [(16384*64)/16];                 // 1 MB fp16 W1 rows, zjS-style swizzle
__device__ int   g_jlist[Bb*Nn];
__device__ int   g_jcnt[Bb];
__device__ int   g_gilist[Bb*Nn];
__device__ int   g_slot[Bb*Nn];
__device__ int   g_total;
__device__ int   g_unit[Bb*Nn*4];                       // (slot<<4)|jt, grouped by slot
__device__ int   g_U;

// ---------------- helpers ----------------
__device__ __forceinline__ uint32_t s2u(const void* p) {
    uint32_t a;
    asm("{ .reg .u64 t; cvta.to.shared.u64 t, %1; cvt.u32.u64 %0, t; }" : "=r"(a) : "l"(p));
    return a;
}
__device__ __forceinline__ void mbar_init(uint32_t m, uint32_t c) {
    asm volatile("mbarrier.init.shared.b64 [%0], %1;" :: "r"(m), "r"(c) : "memory");
}
__device__ __forceinline__ void mbar_expect(uint32_t m, uint32_t bytes) {
    asm volatile("mbarrier.arrive.expect_tx.shared.b64 _, [%0], %1;" :: "r"(m), "r"(bytes) : "memory");
}
__device__ __forceinline__ void mbar_wait(uint32_t m, uint32_t ph) {
    asm volatile(
        "{\n\t.reg .pred P;\n\t"
        "LW%=:\n\t"
        "mbarrier.try_wait.parity.shared.b64 P, [%0], %1, 0x989680;\n\t"
        "@P bra LD%=;\n\t"
        "bra LW%=;\n\t"
        "LD%=:\n\t}"
        :: "r"(m), "r"(ph) : "memory");
}
__device__ __forceinline__ void bulk_g2s(uint32_t dst, const void* src, uint32_t bytes, uint32_t mbar) {
    asm volatile("cp.async.bulk.shared::cluster.global.mbarrier::complete_tx::bytes [%0], [%1], %2, [%3];"
                 :: "r"(dst), "l"(src), "r"(bytes), "r"(mbar) : "memory");
}
__device__ __forceinline__ void mma16816(float d[4], const uint32_t a[4], uint32_t b0, uint32_t b1) {
    asm volatile("mma.sync.aligned.m16n8k16.row.col.f32.f16.f16.f32 "
                 "{%0,%1,%2,%3}, {%4,%5,%6,%7}, {%8,%9}, {%0,%1,%2,%3};"
                 : "+f"(d[0]), "+f"(d[1]), "+f"(d[2]), "+f"(d[3])
                 : "r"(a[0]), "r"(a[1]), "r"(a[2]), "r"(a[3]), "r"(b0), "r"(b1));
}
__device__ __forceinline__ void ldsm4(uint32_t r[4], uint32_t addr) {
    asm volatile("ldmatrix.sync.aligned.m8n8.x4.shared.b16 {%0,%1,%2,%3}, [%4];"
                 : "=r"(r[0]), "=r"(r[1]), "=r"(r[2]), "=r"(r[3]) : "r"(addr));
}

// ---------------- fused prep (out_init + w2t + w1h) ----------------
__global__ void __launch_bounds__(256) prep_all_kernel(float* __restrict__ out,
                                                       const float* __restrict__ W2,
                                                       const float* __restrict__ W1) {
    __shared__ float tile2[16 * 289];
    const int blk = blockIdx.x;
    const int t   = threadIdx.x;

    if (blk < 512) {
        int idx = blk * 256 + t;
        float4* o4 = (float4*)out;
        float v = (idx < 65536) ? 0.5f : 0.f;
        o4[idx] = make_float4(v, v, v, v);
        return;
    }
    if (blk < 768) {
        int idx = (blk - 512) * 256 + t;
        int hc2 = idx >> 12;
        int rem = idx & 4095;
        int k   = rem >> 4;
        int hp  = (rem & 15) * 2;
        int h   = hc2 * 32 + hp;
        __half2 v = __floats2half2_rn(W2[h * Kk + k], W2[(h + 1) * Kk + k]);
        uint32_t byt = (uint32_t)hc2 * 16384u + (uint32_t)k * 64u
                     + (((uint32_t)hp * 2u) ^ ((((uint32_t)k >> 1) & 3u) << 4));
        *(__half2*)((char*)g_w2t + byt) = v;
        return;
    }
    const int q  = blk - 768;
    const int ht = q >> 2;
    const int aq = q & 3;
    #pragma unroll
    for (int l = 0; l < 16; l++) {
        int idx = t + 256 * l;
        int hl = idx & 15, rowl = idx >> 4;
        int a_l = rowl >> 5, c = rowl & 31;
        int grow = (aq * 8 + a_l) * 32 + c;
        tile2[hl * 289 + c * 9 + a_l] = W1[grow * Hh + ht * 16 + hl];
    }
    __syncthreads();
    #pragma unroll
    for (int l = 0; l < 8; l++) {
        int idx = t + 256 * l;
        int a2l = idx & 3, rl = idx >> 2;
        int hl = ((rl >> 6) << 1) + ((rl >> 5) & 1);
        int c  = rl & 31;
        int a2 = aq * 4 + a2l;
        float v0 = tile2[hl * 289 + c * 9 + 2 * a2l];
        float v1 = tile2[hl * 289 + c * 9 + 2 * a2l + 1];
        uint32_t byt = (uint32_t)(ht * 512 + rl) * 64u
                     + (((uint32_t)a2 * 4u) ^ ((((uint32_t)rl >> 1) & 3u) << 4));
        *(__half2*)((char*)g_w1h + byt) = __floats2half2_rn(v0, v1);
    }
}

__global__ void __launch_bounds__(1024) prep_mask_kernel(const float* __restrict__ mm) {
    __shared__ int wcnt[32], woff[33];
    __shared__ int ubase[4], sbase[4], ntl[4];
    int t = threadIdx.x, w = t >> 5, lane = t & 31, b = t >> 8;
    int act = (mm[t] != 0.f);
    unsigned bal = __ballot_sync(0xffffffffu, act);
    if (lane == 0) wcnt[w] = __popc(bal);
    __syncthreads();
    if (t == 0) {
        int s = 0;
        for (int q = 0; q < 32; q++) { woff[q] = s; s += wcnt[q]; }
        woff[32] = s; g_total = s;
        int ub = 0;
        for (int bb = 0; bb < 4; bb++) {
            int jc = woff[bb * 8 + 8] - woff[bb * 8];
            g_jcnt[bb] = jc;
            sbase[bb] = woff[bb * 8];
            int nt = (jc + 63) >> 6;
            ntl[bb] = nt;
            ubase[bb] = ub;
            ub += jc * nt;
        }
        g_U = ub;
    }
    __syncthreads();
    if (act) {
        int pg = woff[w] + __popc(bal & ((1u << lane) - 1u));
        g_jlist[b * Nn + (pg - woff[b * 8])] = t & 255;
        g_gilist[pg] = t;
        g_slot[t] = pg;
        int nt = ntl[b];
        int ub = ubase[b] + (pg - sbase[b]) * nt;
        for (int jt = 0; jt < nt; jt++) g_unit[ub + jt] = (pg << 4) | jt;
    }
}

// TMP via HMMA (unchanged)
#define PM_ZA   0
#define PM_B    4096
#define PM_STG  12288
#define PM_SMEM 20480
__global__ void __launch_bounds__(256) prep_tmpmma_kernel(const float* __restrict__ z) {
    extern __shared__ char psm[];
    __shared__ __align__(8) uint64_t pmb[2];
    __shared__ int giS2[64];

    const int total = g_total;
    const int it = blockIdx.x;
    if (it * 64 >= total) return;
    const int fc = blockIdx.y;
    const int t  = threadIdx.x;
    const int w    = t >> 5;
    const int lane = t & 31;
    const int wr   = w >> 2;
    const int wc   = w & 3;
    const int lr   = lane >> 2;
    const int lc   = (lane & 3) * 2;
    const int mrow = lane & 7;
    const int mg   = lane >> 3;

    const uint32_t smb = s2u(psm);
    const uint32_t mb  = s2u(pmb);

    if (t < 64) giS2[t] = (it * 64 + t < total) ? g_gilist[it * 64 + t] : -1;
    if (t == 0) { mbar_init(mb, 1); mbar_init(mb + 8, 1); }
    __syncthreads();

    if (t < 64) {
        char* zr = psm + PM_ZA + t * 64;
        uint32_t sw = (((uint32_t)t >> 1) & 3u) << 4;
        int gi = giS2[t];
        if (gi >= 0) {
            const float4* zp = (const float4*)(z + (size_t)gi * Dd);
            #pragma unroll
            for (int c4 = 0; c4 < 8; c4++) {
                float4 v = zp[c4];
                *(__half2*)(zr + (((uint32_t)(c4 * 8))     ^ sw)) = __floats2half2_rn(v.x, v.y);
                *(__half2*)(zr + (((uint32_t)(c4 * 8 + 4)) ^ sw)) = __floats2half2_rn(v.z, v.w);
            }
        } else {
            #pragma unroll
            for (int c4 = 0; c4 < 8; c4++) {
                *(__half2*)(zr + (((uint32_t)(c4 * 8))     ^ sw)) = __floats2half2_rn(0.f, 0.f);
                *(__half2*)(zr + (((uint32_t)(c4 * 8 + 4)) ^ sw)) = __floats2half2_rn(0.f, 0.f);
            }
        }
    }
    if (t == 0) {
        mbar_expect(mb, 4096);
        bulk_g2s(smb + PM_B,        (const char*)g_w1h + (size_t)(fc * 16 + 0) * 4096, 4096, mb);
        mbar_expect(mb + 8, 4096);
        bulk_g2s(smb + PM_B + 4096, (const char*)g_w1h + (size_t)(fc * 16 + 1) * 4096, 4096, mb + 8);
    }
    __syncthreads();

    int pw[2] = {0, 0};
    for (int q = 0; q < 16; q++) {
        const int buf = q & 1;
        mbar_wait(mb + buf * 8, pw[buf] & 1); pw[buf]++;
        __syncthreads();

        float acc1[2][2][4];
        #pragma unroll
        for (int mt = 0; mt < 2; mt++)
            #pragma unroll
            for (int nt = 0; nt < 2; nt++)
                #pragma unroll
                for (int e = 0; e < 4; e++) acc1[mt][nt][e] = 0.f;

        const uint32_t bbase = smb + PM_B + (uint32_t)buf * 4096u;
        #pragma unroll
        for (int kk = 0; kk < 2; kk++) {
            const uint32_t cb = (uint32_t)((kk * 16 + (mg >> 1) * 8) * 2);
            uint32_t bf[4];
            {
                int nh = wc * 16 + (mg & 1) * 8 + mrow;
                ldsm4(bf, bbase + (uint32_t)nh * 64u + (cb ^ ((((uint32_t)nh >> 1) & 3u) << 4)));
            }
            #pragma unroll
            for (int mt = 0; mt < 2; mt++) {
                uint32_t af[4];
                int jr = wr * 32 + mt * 16 + (mg & 1) * 8 + mrow;
                ldsm4(af, smb + PM_ZA + (uint32_t)jr * 64u + (cb ^ ((((uint32_t)jr >> 1) & 3u) << 4)));
                mma16816(acc1[mt][0], af, bf[0], bf[2]);
                mma16816(acc1[mt][1], af, bf[1], bf[3]);
            }
        }

        #pragma unroll
        for (int mt = 0; mt < 2; mt++)
            #pragma unroll
            for (int nt = 0; nt < 2; nt++) {
                int rl = wr * 32 + mt * 16 + lr;
                int hl = wc * 16 + nt * 8 + lc;
                uint32_t sw = ((uint32_t)rl & 7u) << 4;
                *(__half2*)(psm + PM_STG + rl * 128 + (((uint32_t)(hl * 2)) ^ sw))
                    = __floats2half2_rn(acc1[mt][nt][0], acc1[mt][nt][1]);
                *(__half2*)(psm + PM_STG + (rl + 8) * 128 + (((uint32_t)(hl * 2)) ^ sw))
                    = __floats2half2_rn(acc1[mt][nt][2], acc1[mt][nt][3]);
            }
        __syncthreads();

        if (t == 0 && q + 2 < 16) {
            mbar_expect(mb + buf * 8, 4096);
            bulk_g2s(smb + PM_B + (uint32_t)buf * 4096u,
                     (const char*)g_w1h + (size_t)(fc * 16 + q + 2) * 4096, 4096, mb + buf * 8);
        }

        const int qg = fc * 16 + q;
        #pragma unroll
        for (int l = 0; l < 2; l++) {
            int idx = t + 256 * l;
            int sl = idx >> 3, qt = idx & 7;
            int s = it * 64 + sl;
            if (s < total) {
                uint4 v = *(const uint4*)(psm + PM_STG + sl * 128 + ((qt * 16) ^ ((sl & 7) << 4)));
                *(uint4*)((char*)g_tmph + (size_t)s * 32768 + qg * 128 + qt * 16) = v;
            }
        }
    }
}

// ---------------- main kernel (persistent, R13 skeleton + 3-slot W2 ring, full-chunk TMA lead) ----------------
// dyn smem: zjS 4K @0 | tmpS 32K @4096 | W2 ring 3x16K @36864 | h1 2x8K @86016 = 102400
#define ZJ_OFF  0
#define TMP_OFF 4096
#define W2_OFF  36864
#define H1_OFF  86016
#define MAIN_SMEM 102400

__global__ void __launch_bounds__(256, 2)
decoder_hmma_kernel(const float* __restrict__ z, const float* __restrict__ b1,
                    const float* __restrict__ b2, const float* __restrict__ W3,
                    const float* __restrict__ b3, float* __restrict__ out)
{
    extern __shared__ char dsm[];
    __shared__ float b1s[512], b2s[256], w3s[256], part[64];
    __shared__ int jlS[256];
    __shared__ __align__(8) uint64_t mbars[3];

    const int t    = threadIdx.x;
    const int w    = t >> 5;
    const int lane = t & 31;
    const int wr   = w >> 2;
    const int wc   = w & 3;
    const int lr   = lane >> 2;
    const int lc   = (lane & 3) * 2;
    const int mrow = lane & 7;
    const int mg   = lane >> 3;

    const int U  = g_U;
    const int u0 = (int)(((long long)blockIdx.x * U) / GRID_MAIN);
    const int u1 = (int)(((long long)(blockIdx.x + 1) * U) / GRID_MAIN);
    if (u0 >= u1) return;
    const int totalQ = (u1 - u0) * 16;

    const uint32_t smb = s2u(dsm);
    const uint32_t mb0 = s2u(mbars);

    for (int k = t; k < 512; k += 256) b1s[k] = b1[k];
    b2s[t] = b2[t];
    w3s[t] = W3[t];
    if (t == 0) { mbar_init(mb0, 1); mbar_init(mb0 + 8, 1); mbar_init(mb0 + 16, 1); }
    __syncthreads();
    if (t == 0) {                       // prime ring: subs 0,1,2 -> slots 0,1,2
        int np = totalQ < 3 ? totalQ : 3;
        for (int q = 0; q < np; q++) {
            mbar_expect(mb0 + 8u * q, 16384);
            bulk_g2s(smb + W2_OFF + (uint32_t)q * 16384u,
                     (const char*)g_w2t + (q & 15) * 16384, 16384, mb0 + 8u * q);
        }
    }

    const float b3v = b3[0];
    int C = 0;
    int bprev = -1, sprev = -1;

    for (int u = u0; u < u1; u++) {
        const int enc = g_unit[u];
        const int s   = enc >> 4;
        const int jt  = enc & 15;
        const int gi  = g_gilist[s];
        const int b   = gi >> 8;

        if (b != bprev) {
            jlS[t] = g_jlist[b * Nn + t];
            bprev = b;
            __syncthreads();
        }
        const int Kact = g_jcnt[b];

        if (s != sprev) {               // tmpS: 512 rows x 64B, swizzle ((row>>1)&3)<<4
            const char* gsrc = (const char*)g_tmph + (size_t)s * 32768;
            #pragma unroll
            for (int r8 = 0; r8 < 8; r8++) {
                int idx = t + 256 * r8;
                int row = idx >> 2, q = idx & 3;
                uint4 v = *(const uint4*)(gsrc + row * 64 + q * 16);
                *(uint4*)(dsm + TMP_OFF + row * 64 + ((q * 16) ^ (((row >> 1) & 3) << 4))) = v;
            }
            sprev = s;
        }

        if (t < 64) {                   // zjS + part zero
            part[t] = 0.f;
            int idx = jt * 64 + t;
            char* zr = dsm + ZJ_OFF + t * 64;
            uint32_t sw = (((uint32_t)t >> 1) & 3u) << 4;
            if (idx < Kact) {
                const float4* zp = (const float4*)(z + ((size_t)b * Nn + jlS[idx]) * Dd);
                #pragma unroll
                for (int c4 = 0; c4 < 8; c4++) {
                    float4 v = zp[c4];
                    *(__half2*)(zr + (((uint32_t)(c4 * 8))     ^ sw)) = __floats2half2_rn(v.x, v.y);
                    *(__half2*)(zr + (((uint32_t)(c4 * 8 + 4)) ^ sw)) = __floats2half2_rn(v.z, v.w);
                }
            } else {
                #pragma unroll
                for (int c4 = 0; c4 < 8; c4++) {
                    *(__half2*)(zr + (((uint32_t)(c4 * 8))     ^ sw)) = __floats2half2_rn(0.f, 0.f);
                    *(__half2*)(zr + (((uint32_t)(c4 * 8 + 4)) ^ sw)) = __floats2half2_rn(0.f, 0.f);
                }
            }
        }
        __syncthreads();

        float acc2[2][8][4];
        #pragma unroll
        for (int mt = 0; mt < 2; mt++)
            #pragma unroll
            for (int nt = 0; nt < 8; nt++)
                #pragma unroll
                for (int e = 0; e < 4; e++) acc2[mt][nt][e] = 0.f;

        for (int hc = 0; hc < 8; hc++) {
            const int q0 = 2 * C, q1 = 2 * C + 1;
            const uint32_t s0 = (uint32_t)(q0 % 3), s1 = (uint32_t)(q1 % 3);

            // ---- MMA1 (64h) into regs ----
            float acc1[2][2][4];
            #pragma unroll
            for (int mt = 0; mt < 2; mt++)
                #pragma unroll
                for (int nt = 0; nt < 2; nt++)
                    #pragma unroll
                    for (int e = 0; e < 4; e++) acc1[mt][nt][e] = 0.f;

            #pragma unroll
            for (int kk = 0; kk < 2; kk++) {
                const uint32_t cb = (uint32_t)((kk * 16 + (mg >> 1) * 8) * 2);
                uint32_t bf[4];
                {
                    int nh = hc * 64 + wc * 16 + (mg & 1) * 8 + mrow;
                    ldsm4(bf, smb + TMP_OFF + (uint32_t)nh * 64u + (cb ^ ((((uint32_t)nh >> 1) & 3u) << 4)));
                }
                #pragma unroll
                for (int mt = 0; mt < 2; mt++) {
                    uint32_t af[4];
                    int jr = wr * 32 + mt * 16 + (mg & 1) * 8 + mrow;
                    ldsm4(af, smb + ZJ_OFF + (uint32_t)jr * 64u + (cb ^ ((((uint32_t)jr >> 1) & 3u) << 4)));
                    mma16816(acc1[mt][0], af, bf[0], bf[2]);
                    mma16816(acc1[mt][1], af, bf[1], bf[3]);
                }
            }

            // ---- h1 store into double buffer C&1 ----
            char* h1p = dsm + H1_OFF + (C & 1) * 8192;
            const uint32_t h1b = smb + H1_OFF + (uint32_t)(C & 1) * 8192u;
            #pragma unroll
            for (int mt = 0; mt < 2; mt++)
                #pragma unroll
                for (int nt = 0; nt < 2; nt++) {
                    int rl = wr * 32 + mt * 16 + lr;
                    int hl = wc * 16 + nt * 8 + lc;
                    int hg = hc * 64 + hl;
                    uint32_t sw = ((uint32_t)rl & 7u) << 4;
                    float v0 = fmaxf(acc1[mt][nt][0] + b1s[hg],     0.f);
                    float v1 = fmaxf(acc1[mt][nt][1] + b1s[hg + 1], 0.f);
                    float v2 = fmaxf(acc1[mt][nt][2] + b1s[hg],     0.f);
                    float v3 = fmaxf(acc1[mt][nt][3] + b1s[hg + 1], 0.f);
                    *(__half2*)(h1p + rl * 128 + (((uint32_t)(hl * 2)) ^ sw))       = __floats2half2_rn(v0, v1);
                    *(__half2*)(h1p + (rl + 8) * 128 + (((uint32_t)(hl * 2)) ^ sw)) = __floats2half2_rn(v2, v3);
                }

            mbar_wait(mb0 + s0 * 8u, (q0 / 3) & 1);
            __syncthreads();            // syncA: h1 visible; prev chunk's MMA2-B ring reads done

            if (t == 0) {               // prefetch q0+2 into slot freed by prev chunk's MMA2-B
                int qa = q0 + 2;
                if (qa >= 3 && qa < totalQ) {
                    mbar_expect(mb0 + (uint32_t)(qa % 3) * 8u, 16384);
                    bulk_g2s(smb + W2_OFF + (uint32_t)(qa % 3) * 16384u,
                             (const char*)g_w2t + (qa & 15) * 16384, 16384,
                             mb0 + (uint32_t)(qa % 3) * 8u);
                }
            }

            // ---- MMA2 half A (W2 slot s0) ----
            const uint32_t sb0 = smb + W2_OFF + s0 * 16384u;
            #pragma unroll
            for (int kk = 0; kk < 2; kk++) {
                const uint32_t kb = (uint32_t)((kk * 16 + (mg >> 1) * 8) * 2);
                uint32_t bfs[4][4];
                #pragma unroll
                for (int p = 0; p < 4; p++) {
                    int n = wc * 64 + p * 16 + (mg & 1) * 8 + mrow;
                    ldsm4(bfs[p], sb0 + (uint32_t)n * 64u + (kb ^ ((((uint32_t)n >> 1) & 3u) << 4)));
                }
                #pragma unroll
                for (int mt = 0; mt < 2; mt++) {
                    uint32_t af[4];
                    int rl = wr * 32 + mt * 16 + (mg & 1) * 8 + mrow;
                    ldsm4(af, h1b + (uint32_t)rl * 128u + (kb ^ (((uint32_t)rl & 7u) << 4)));
                    #pragma unroll
                    for (int p = 0; p < 4; p++) {
                        mma16816(acc2[mt][2 * p],     af, bfs[p][0], bfs[p][2]);
                        mma16816(acc2[mt][2 * p + 1], af, bfs[p][1], bfs[p][3]);
                    }
                }
            }

            __syncthreads();            // syncB: slot s0 reads done
            if (t == 0) {               // prefetch q1+2 into slot s0 (just freed)
                int qb = q1 + 2;
                if (qb < totalQ) {
                    mbar_expect(mb0 + (uint32_t)(qb % 3) * 8u, 16384);
                    bulk_g2s(smb + W2_OFF + (uint32_t)(qb % 3) * 16384u,
                             (const char*)g_w2t + (qb & 15) * 16384, 16384,
                             mb0 + (uint32_t)(qb % 3) * 8u);
                }
            }
            mbar_wait(mb0 + s1 * 8u, (q1 / 3) & 1);

            // ---- MMA2 half B (W2 slot s1, h1 upper 32 h) ----
            const uint32_t sb1 = smb + W2_OFF + s1 * 16384u;
            #pragma unroll
            for (int kk = 0; kk < 2; kk++) {
                const uint32_t kb  = (uint32_t)((kk * 16 + (mg >> 1) * 8) * 2);
                const uint32_t ccb = kb + 64u;
                uint32_t bfs[4][4];
                #pragma unroll
                for (int p = 0; p < 4; p++) {
                    int n = wc * 64 + p * 16 + (mg & 1) * 8 + mrow;
                    ldsm4(bfs[p], sb1 + (uint32_t)n * 64u + (kb ^ ((((uint32_t)n >> 1) & 3u) << 4)));
                }
                #pragma unroll
                for (int mt = 0; mt < 2; mt++) {
                    uint32_t af[4];
                    int rl = wr * 32 + mt * 16 + (mg & 1) * 8 + mrow;
                    ldsm4(af, h1b + (uint32_t)rl * 128u + (ccb ^ (((uint32_t)rl & 7u) << 4)));
                    #pragma unroll
                    for (int p = 0; p < 4; p++) {
                        mma16816(acc2[mt][2 * p],     af, bfs[p][0], bfs[p][2]);
                        mma16816(acc2[mt][2 * p + 1], af, bfs[p][1], bfs[p][3]);
                    }
                }
            }
            C++;
        }

        // ---- epilogue ----
        float sacc[2][2] = {{0.f, 0.f}, {0.f, 0.f}};
        #pragma unroll
        for (int mt = 0; mt < 2; mt++)
            #pragma unroll
            for (int nt = 0; nt < 8; nt++) {
                int k = wc * 64 + nt * 8 + lc;
                sacc[mt][0] += fmaxf(acc2[mt][nt][0] + b2s[k],     0.f) * w3s[k]
                             + fmaxf(acc2[mt][nt][1] + b2s[k + 1], 0.f) * w3s[k + 1];
                sacc[mt][1] += fmaxf(acc2[mt][nt][2] + b2s[k],     0.f) * w3s[k]
                             + fmaxf(acc2[mt][nt][3] + b2s[k + 1], 0.f) * w3s[k + 1];
            }
        #pragma unroll
        for (int off = 1; off <= 2; off <<= 1) {
            #pragma unroll
            for (int mt = 0; mt < 2; mt++) {
                sacc[mt][0] += __shfl_xor_sync(0xffffffffu, sacc[mt][0], off);
                sacc[mt][1] += __shfl_xor_sync(0xffffffffu, sacc[mt][1], off);
            }
        }
        if ((lane & 3) == 0) {
            #pragma unroll
            for (int mt = 0; mt < 2; mt++) {
                int r0 = wr * 32 + mt * 16 + lr;
                atomicAdd(&part[r0],     sacc[mt][0]);
                atomicAdd(&part[r0 + 8], sacc[mt][1]);
            }
        }
        __syncthreads();
        if (t < 64) {
            int idx = jt * 64 + t;
            if (idx < Kact) {
                int j = jlS[idx];
                float lg = part[t] + b3v;
                size_t o = (size_t)gi * Nn + j;
                out[o] = 1.f / (1.f + __expf(-lg));
                out[(size_t)Bb * Nn * Nn + o] = lg;
            }
        }
        __syncthreads();
    }
}

extern "C" void kernel_launch(void* const* d_in, const int* in_sizes, int n_in,
                              void* d_out, int out_size)
{
    const float* z   = (const float*)d_in[0];
    const float* mmk = (const float*)d_in[1];
    const float* W1  = (const float*)d_in[3];
    const float* b1  = (const float*)d_in[4];
    const float* W2  = (const float*)d_in[5];
    const float* b2  = (const float*)d_in[6];
    const float* W3  = (const float*)d_in[7];
    const float* b3  = (const float*)d_in[8];
    float* out = (float*)d_out;

    cudaFuncSetAttribute(decoder_hmma_kernel,
                         cudaFuncAttributeMaxDynamicSharedMemorySize, MAIN_SMEM);

    prep_all_kernel<<<896, 256>>>(out, W2, W1);
    prep_mask_kernel<<<1, 1024>>>(mmk);
    prep_tmpmma_kernel<<<dim3(8, 16), 256, PM_SMEM>>>(z);
    decoder_hmma_kernel<<<GRID_MAIN, 256, MAIN_SMEM>>>(z, b1, b2, W3, b3, out);
}